// round 1
// baseline (speedup 1.0000x reference)
#include <cuda_runtime.h>
#include <math.h>

#define BB 4
#define SS 2048
#define DD 768
#define HH 12
#define HD 64
#define QK_SCALE 0.125f   // 64^-0.5

#define M_TOK (BB*SS)     // 8192

// Scratch (no cudaMalloc allowed): QKV projection result and attention context.
__device__ float g_qkv[(size_t)M_TOK * 3 * DD];  // [B,S,3,H,HD] == [M, 3D] row-major
__device__ float g_ctx[(size_t)M_TOK * DD];      // [B,S,D]

// ---------------------------------------------------------------------------
// Dense GEMM: C[M,N] = A[M,K] @ B[K,N] (+ bias). 128x128x16 tiles, 8x8 micro.
// M,N multiples of 128; K multiple of 16. 256 threads.
// ---------------------------------------------------------------------------
template<bool BIAS>
__global__ void __launch_bounds__(256, 2)
gemm128_kernel(const float* __restrict__ A, const float* __restrict__ Bm,
               const float* __restrict__ bias, float* __restrict__ C,
               int M, int N, int K)
{
    __shared__ float As[16][132];   // [k][m], padded
    __shared__ float Bs[16][132];   // [k][n], padded

    const int t  = threadIdx.x;
    const int tx = t & 15;
    const int ty = t >> 4;
    const int m0 = blockIdx.y * 128;
    const int n0 = blockIdx.x * 128;

    const int atm = t & 127;          // A row within tile
    const int atk = (t >> 7) * 8;     // A k-chunk (0 or 8)
    const int btn = (t & 31) * 4;     // B n within tile
    const int btk = t >> 5;           // B k row (0..7), +8 for second

    float acc[8][8];
    #pragma unroll
    for (int i = 0; i < 8; i++)
        #pragma unroll
        for (int j = 0; j < 8; j++) acc[i][j] = 0.f;

    for (int k0 = 0; k0 < K; k0 += 16) {
        float4 a0 = *(const float4*)&A[(size_t)(m0 + atm) * K + k0 + atk];
        float4 a1 = *(const float4*)&A[(size_t)(m0 + atm) * K + k0 + atk + 4];
        As[atk + 0][atm] = a0.x; As[atk + 1][atm] = a0.y;
        As[atk + 2][atm] = a0.z; As[atk + 3][atm] = a0.w;
        As[atk + 4][atm] = a1.x; As[atk + 5][atm] = a1.y;
        As[atk + 6][atm] = a1.z; As[atk + 7][atm] = a1.w;

        float4 b0 = *(const float4*)&Bm[(size_t)(k0 + btk) * N + n0 + btn];
        float4 b1 = *(const float4*)&Bm[(size_t)(k0 + btk + 8) * N + n0 + btn];
        *(float4*)&Bs[btk][btn]     = b0;
        *(float4*)&Bs[btk + 8][btn] = b1;

        __syncthreads();

        #pragma unroll
        for (int k = 0; k < 16; k++) {
            float av[8], bv[8];
            *(float4*)&av[0] = *(const float4*)&As[k][ty * 8];
            *(float4*)&av[4] = *(const float4*)&As[k][ty * 8 + 4];
            *(float4*)&bv[0] = *(const float4*)&Bs[k][tx * 8];
            *(float4*)&bv[4] = *(const float4*)&Bs[k][tx * 8 + 4];
            #pragma unroll
            for (int i = 0; i < 8; i++)
                #pragma unroll
                for (int j = 0; j < 8; j++)
                    acc[i][j] += av[i] * bv[j];
        }
        __syncthreads();
    }

    #pragma unroll
    for (int i = 0; i < 8; i++) {
        size_t row = (size_t)(m0 + ty * 8 + i);
        #pragma unroll
        for (int jj = 0; jj < 8; jj += 4) {
            float4 v;
            v.x = acc[i][jj + 0]; v.y = acc[i][jj + 1];
            v.z = acc[i][jj + 2]; v.w = acc[i][jj + 3];
            if (BIAS) {
                const float4 bvv = *(const float4*)&bias[n0 + tx * 8 + jj];
                v.x += bvv.x; v.y += bvv.y; v.z += bvv.z; v.w += bvv.w;
            }
            *(float4*)&C[row * N + n0 + tx * 8 + jj] = v;
        }
    }
}

// ---------------------------------------------------------------------------
// Flash attention: per (b,h), 64-row query blocks stream over 64-row KV blocks.
// Tiles stored d-major so both GEMMs use float4 smem fragments.
// smem: Qs[64][68] (d-major) | Ks[64][68] (d-major, reused as P c-major) |
//       Vs[64][68] (c-major/row)  -> 52224 bytes dynamic.
// ---------------------------------------------------------------------------
#define TPAD 68
#define SMEM_ATTN (3 * 64 * TPAD * 4)

__global__ void __launch_bounds__(256, 2)
attn_kernel()
{
    extern __shared__ float smem[];
    float* Qs = smem;
    float* Ks = smem + 64 * TPAD;   // also holds P after scores consumed
    float* Vs = smem + 2 * 64 * TPAD;

    const int t  = threadIdx.x;
    const int tx = t & 15;
    const int ty = t >> 4;
    const int bh = blockIdx.y;
    const int b  = bh / HH;
    const int h  = bh % HH;
    const int qb = blockIdx.x;

    const int rr  = t & 63;          // row handled by this thread in tile loads
    const int dd0 = (t >> 6) * 16;   // d-chunk start

    // --- load Q tile (scaled), store d-major ---
    {
        const float* qrow = g_qkv + ((size_t)(b * SS + qb * 64 + rr) * 3 * DD) + h * HD;
        #pragma unroll
        for (int i = 0; i < 4; i++) {
            float4 v = *(const float4*)(qrow + dd0 + i * 4);
            Qs[(dd0 + i * 4 + 0) * TPAD + rr] = v.x * QK_SCALE;
            Qs[(dd0 + i * 4 + 1) * TPAD + rr] = v.y * QK_SCALE;
            Qs[(dd0 + i * 4 + 2) * TPAD + rr] = v.z * QK_SCALE;
            Qs[(dd0 + i * 4 + 3) * TPAD + rr] = v.w * QK_SCALE;
        }
    }

    float m[4], l[4], o[4][4];
    #pragma unroll
    for (int i = 0; i < 4; i++) {
        m[i] = -1e30f; l[i] = 0.f;
        #pragma unroll
        for (int j = 0; j < 4; j++) o[i][j] = 0.f;
    }

    for (int jb = 0; jb < SS / 64; jb++) {
        __syncthreads();   // prior-iter smem reads done (and Q visible on iter 0 after next sync)

        // --- load K (d-major) and V (row-major) tiles ---
        const float* krow = g_qkv + ((size_t)(b * SS + jb * 64 + rr) * 3 * DD) + DD + h * HD;
        const float* vrow = krow + DD;
        #pragma unroll
        for (int i = 0; i < 4; i++) {
            float4 kv = *(const float4*)(krow + dd0 + i * 4);
            Ks[(dd0 + i * 4 + 0) * TPAD + rr] = kv.x;
            Ks[(dd0 + i * 4 + 1) * TPAD + rr] = kv.y;
            Ks[(dd0 + i * 4 + 2) * TPAD + rr] = kv.z;
            Ks[(dd0 + i * 4 + 3) * TPAD + rr] = kv.w;
            float4 vv = *(const float4*)(vrow + dd0 + i * 4);
            *(float4*)&Vs[rr * TPAD + dd0 + i * 4] = vv;
        }
        __syncthreads();

        // --- S = Q @ K^T (reduction over d) ---
        float sa[4][4];
        #pragma unroll
        for (int i = 0; i < 4; i++)
            #pragma unroll
            for (int j = 0; j < 4; j++) sa[i][j] = 0.f;

        #pragma unroll 16
        for (int d = 0; d < 64; d++) {
            float av[4], bv[4];
            *(float4*)&av[0] = *(const float4*)&Qs[d * TPAD + ty * 4];
            *(float4*)&bv[0] = *(const float4*)&Ks[d * TPAD + tx * 4];
            #pragma unroll
            for (int i = 0; i < 4; i++)
                #pragma unroll
                for (int j = 0; j < 4; j++)
                    sa[i][j] += av[i] * bv[j];
        }

        // --- online softmax (stats in registers, 16-lane shuffle reduce) ---
        #pragma unroll
        for (int i = 0; i < 4; i++) {
            float rm = fmaxf(fmaxf(sa[i][0], sa[i][1]), fmaxf(sa[i][2], sa[i][3]));
            #pragma unroll
            for (int off = 8; off > 0; off >>= 1)
                rm = fmaxf(rm, __shfl_xor_sync(0xffffffffu, rm, off, 16));
            const float mn   = fmaxf(m[i], rm);
            const float corr = __expf(m[i] - mn);
            float rs = 0.f;
            #pragma unroll
            for (int j = 0; j < 4; j++) {
                sa[i][j] = __expf(sa[i][j] - mn);
                rs += sa[i][j];
            }
            #pragma unroll
            for (int off = 8; off > 0; off >>= 1)
                rs += __shfl_xor_sync(0xffffffffu, rs, off, 16);
            l[i] = l[i] * corr + rs;
            m[i] = mn;
            #pragma unroll
            for (int j = 0; j < 4; j++) o[i][j] *= corr;
        }

        __syncthreads();   // everyone done reading Ks
        // --- write P (c-major) into Ks buffer ---
        #pragma unroll
        for (int i = 0; i < 4; i++)
            #pragma unroll
            for (int j = 0; j < 4; j++)
                Ks[(tx * 4 + j) * TPAD + ty * 4 + i] = sa[i][j];
        __syncthreads();

        // --- O += P @ V (reduction over c) ---
        #pragma unroll 16
        for (int c = 0; c < 64; c++) {
            float av[4], bv[4];
            *(float4*)&av[0] = *(const float4*)&Ks[c * TPAD + ty * 4];
            *(float4*)&bv[0] = *(const float4*)&Vs[c * TPAD + tx * 4];
            #pragma unroll
            for (int i = 0; i < 4; i++)
                #pragma unroll
                for (int j = 0; j < 4; j++)
                    o[i][j] += av[i] * bv[j];
        }
    }

    // --- normalize and write context: ctx[b, s, h*64 + d] ---
    #pragma unroll
    for (int i = 0; i < 4; i++) {
        const float inv = 1.0f / l[i];
        const int row = qb * 64 + ty * 4 + i;
        float4 st;
        st.x = o[i][0] * inv; st.y = o[i][1] * inv;
        st.z = o[i][2] * inv; st.w = o[i][3] * inv;
        *(float4*)&g_ctx[(size_t)(b * SS + row) * DD + h * HD + tx * 4] = st;
    }
}

// ---------------------------------------------------------------------------
extern "C" void kernel_launch(void* const* d_in, const int* in_sizes, int n_in,
                              void* d_out, int out_size)
{
    const float* x     = (const float*)d_in[0];
    const float* w_qkv = (const float*)d_in[1];
    const float* w_out = (const float*)d_in[2];
    const float* b_out = (const float*)d_in[3];
    float* out = (float*)d_out;

    float* qkv_ptr = nullptr;
    float* ctx_ptr = nullptr;
    cudaGetSymbolAddress((void**)&qkv_ptr, g_qkv);
    cudaGetSymbolAddress((void**)&ctx_ptr, g_ctx);

    cudaFuncSetAttribute(attn_kernel, cudaFuncAttributeMaxDynamicSharedMemorySize,
                         SMEM_ATTN);

    // 1) QKV projection: [8192,768] @ [768,2304]
    gemm128_kernel<false><<<dim3(3 * DD / 128, M_TOK / 128), 256>>>(
        x, w_qkv, nullptr, qkv_ptr, M_TOK, 3 * DD, DD);

    // 2) flash attention over all (b,h) and query blocks
    attn_kernel<<<dim3(SS / 64, BB * HH), 256, SMEM_ATTN>>>();

    // 3) output projection + bias: [8192,768] @ [768,768]
    gemm128_kernel<true><<<dim3(DD / 128, M_TOK / 128), 256>>>(
        ctx_ptr, w_out, b_out, out, M_TOK, DD, DD);
}

// round 2
// speedup vs baseline: 1.3800x; 1.3800x over previous
#include <cuda_runtime.h>
#include <math.h>

#define BB 4
#define SS 2048
#define DD 768
#define HH 12
#define HD 64
#define QK_SCALE 0.125f
#define M_TOK (BB*SS)

// Scratch (no cudaMalloc allowed)
__device__ float g_qkv[(size_t)M_TOK * 3 * DD];  // [B,S,3,H,HD]
__device__ float g_ctx[(size_t)M_TOK * DD];      // [B,S,D]

__device__ __forceinline__ unsigned f2tf(float x) {
    unsigned r; asm("cvt.rna.tf32.f32 %0, %1;" : "=r"(r) : "f"(x)); return r;
}
__device__ __forceinline__ void mma8(float c[4], const unsigned a[4],
                                     unsigned b0, unsigned b1) {
    asm volatile(
        "mma.sync.aligned.m16n8k8.row.col.f32.tf32.tf32.f32 "
        "{%0,%1,%2,%3},{%4,%5,%6,%7},{%8,%9},{%0,%1,%2,%3};"
        : "+f"(c[0]), "+f"(c[1]), "+f"(c[2]), "+f"(c[3])
        : "r"(a[0]), "r"(a[1]), "r"(a[2]), "r"(a[3]), "r"(b0), "r"(b1));
}
__device__ __forceinline__ void split4(const float4& v, uint4& hi, uint4& lo) {
    hi.x = f2tf(v.x); lo.x = f2tf(v.x - __uint_as_float(hi.x));
    hi.y = f2tf(v.y); lo.y = f2tf(v.y - __uint_as_float(hi.y));
    hi.z = f2tf(v.z); lo.z = f2tf(v.z - __uint_as_float(hi.z));
    hi.w = f2tf(v.w); lo.w = f2tf(v.w - __uint_as_float(hi.w));
}

// ---------------------------------------------------------------------------
// Dense GEMM, split-tf32 (near-fp32 accuracy): C = A[M,K] @ B[K,N] (+bias)
// 128x128 block, 8 warps of 64x32, k-tile 16.
// ---------------------------------------------------------------------------
#define ASTR 20
#define BSTR 136

template<bool BIAS>
__global__ void __launch_bounds__(256)
gemm_tc(const float* __restrict__ A, const float* __restrict__ Bm,
        const float* __restrict__ bias, float* __restrict__ C,
        int M, int N, int K)
{
    __shared__ unsigned Ah[128 * ASTR], Al[128 * ASTR];
    __shared__ unsigned Bh[16 * BSTR],  Bl[16 * BSTR];

    const int t = threadIdx.x, lane = t & 31, warp = t >> 5;
    const int g = lane >> 2, tg = lane & 3;
    const int m0 = blockIdx.y * 128, n0 = blockIdx.x * 128;
    const int wm = (warp >> 2) * 64, wn = (warp & 3) * 32;

    const int arow = t >> 1, acol = (t & 1) * 8;   // A: 128 rows x 16 k
    const int bk = t >> 4,  bn = (t & 15) * 8;     // B: 16 k x 128 n

    const float* Ap = A + (size_t)(m0 + arow) * K + acol;
    const float* Bp = Bm + (size_t)bk * N + n0 + bn;

    float4 ra0 = *(const float4*)Ap;
    float4 ra1 = *(const float4*)(Ap + 4);
    float4 rb0 = *(const float4*)Bp;
    float4 rb1 = *(const float4*)(Bp + 4);

    float acc[4][4][4];
    #pragma unroll
    for (int i = 0; i < 4; i++)
        #pragma unroll
        for (int j = 0; j < 4; j++)
            #pragma unroll
            for (int k = 0; k < 4; k++) acc[i][j][k] = 0.f;

    for (int k0 = 0; k0 < K; k0 += 16) {
        {   // split + store staged tile
            uint4 h, l;
            const int ab = arow * ASTR + acol;
            split4(ra0, h, l);
            *(uint4*)&Ah[ab] = h;     *(uint4*)&Al[ab] = l;
            split4(ra1, h, l);
            *(uint4*)&Ah[ab + 4] = h; *(uint4*)&Al[ab + 4] = l;
            const int bb = bk * BSTR + bn;
            split4(rb0, h, l);
            *(uint4*)&Bh[bb] = h;     *(uint4*)&Bl[bb] = l;
            split4(rb1, h, l);
            *(uint4*)&Bh[bb + 4] = h; *(uint4*)&Bl[bb + 4] = l;
        }
        __syncthreads();
        if (k0 + 16 < K) {
            Ap += 16; Bp += (size_t)16 * N;
            ra0 = *(const float4*)Ap;  ra1 = *(const float4*)(Ap + 4);
            rb0 = *(const float4*)Bp;  rb1 = *(const float4*)(Bp + 4);
        }
        #pragma unroll
        for (int s = 0; s < 2; s++) {
            unsigned ah[4][4], al[4][4];
            #pragma unroll
            for (int ma = 0; ma < 4; ma++) {
                const int base = (wm + ma * 16 + g) * ASTR + s * 8 + tg;
                ah[ma][0] = Ah[base];            ah[ma][1] = Ah[base + 8 * ASTR];
                ah[ma][2] = Ah[base + 4];        ah[ma][3] = Ah[base + 8 * ASTR + 4];
                al[ma][0] = Al[base];            al[ma][1] = Al[base + 8 * ASTR];
                al[ma][2] = Al[base + 4];        al[ma][3] = Al[base + 8 * ASTR + 4];
            }
            #pragma unroll
            for (int na = 0; na < 4; na++) {
                const int kb = (s * 8 + tg) * BSTR + wn + na * 8 + g;
                const unsigned bh0 = Bh[kb], bh1 = Bh[kb + 4 * BSTR];
                const unsigned bl0 = Bl[kb], bl1 = Bl[kb + 4 * BSTR];
                #pragma unroll
                for (int ma = 0; ma < 4; ma++) {
                    mma8(acc[ma][na], ah[ma], bh0, bh1);
                    mma8(acc[ma][na], ah[ma], bl0, bl1);
                    mma8(acc[ma][na], al[ma], bh0, bh1);
                }
            }
        }
        __syncthreads();
    }

    #pragma unroll
    for (int ma = 0; ma < 4; ma++) {
        #pragma unroll
        for (int na = 0; na < 4; na++) {
            const int row = m0 + wm + ma * 16 + g;
            const int col = n0 + wn + na * 8 + 2 * tg;
            float bx = 0.f, by = 0.f;
            if (BIAS) { bx = bias[col]; by = bias[col + 1]; }
            float2 v0 = make_float2(acc[ma][na][0] + bx, acc[ma][na][1] + by);
            float2 v1 = make_float2(acc[ma][na][2] + bx, acc[ma][na][3] + by);
            *(float2*)&C[(size_t)row * N + col] = v0;
            *(float2*)&C[(size_t)(row + 8) * N + col] = v1;
        }
    }
}

// ---------------------------------------------------------------------------
// Flash attention, tensor-core tf32.
// Block = 64 q rows x (b,h); 4 warps, each owns 16 q rows.
// QK^T in split-tf32 (Q-hi in regs, Q-lo/K-hi/K-lo in smem); PV single tf32.
// P overwrites the K-hi buffer between barriers.
// ---------------------------------------------------------------------------
#define QSTR 68
#define KSTR 68
#define VSTR 72
#define ATT_SMEM ((64*QSTR + 2*64*KSTR + 64*VSTR) * 4)

__global__ void __launch_bounds__(128)
attn_tc()
{
    extern __shared__ unsigned smu[];
    unsigned* Ql  = smu;                 // Q lo [64][QSTR]
    unsigned* KhP = smu + 64 * QSTR;     // K hi / P tile [64][KSTR]
    unsigned* Kl  = KhP + 64 * KSTR;     // K lo [64][KSTR]
    unsigned* Vs  = Kl  + 64 * KSTR;     // V    [64][VSTR]

    const int t = threadIdx.x, lane = t & 31, warp = t >> 5;
    const int g = lane >> 2, tg = lane & 3;
    const int b = blockIdx.y / HH, h = blockIdx.y % HH, qb = blockIdx.x;

    const size_t tok0 = (size_t)b * SS + qb * 64;

    // ---- stage Q: hi -> KhP (temporary), lo -> Ql ----
    {
        const int row = t >> 1, c0 = (t & 1) * 32;
        const float* qr = g_qkv + (tok0 + row) * (3 * DD) + h * HD + c0;
        #pragma unroll
        for (int j = 0; j < 8; j++) {
            float4 v = *(const float4*)(qr + j * 4);
            v.x *= QK_SCALE; v.y *= QK_SCALE; v.z *= QK_SCALE; v.w *= QK_SCALE;
            uint4 hi, lo; split4(v, hi, lo);
            *(uint4*)&KhP[row * KSTR + c0 + j * 4] = hi;
            *(uint4*)&Ql [row * QSTR + c0 + j * 4] = lo;
        }
    }
    __syncthreads();
    unsigned qh[8][4];
    #pragma unroll
    for (int s = 0; s < 8; s++) {
        const int base = (warp * 16 + g) * KSTR + s * 8 + tg;
        qh[s][0] = KhP[base];     qh[s][1] = KhP[base + 8 * KSTR];
        qh[s][2] = KhP[base + 4]; qh[s][3] = KhP[base + 8 * KSTR + 4];
    }
    __syncthreads();

    float mrow[2] = {-1e30f, -1e30f}, lrow[2] = {0.f, 0.f};
    float oacc[8][4];
    #pragma unroll
    for (int i = 0; i < 8; i++)
        #pragma unroll
        for (int j = 0; j < 4; j++) oacc[i][j] = 0.f;

    const float* kvbase = g_qkv + ((size_t)b * SS) * (3 * DD) + DD + h * HD;

    for (int jb = 0; jb < SS / 64; jb++) {
        // ---- stage K (split) and V (tf32) ----
        {
            const int row = t >> 1, c0 = (t & 1) * 32;
            const float* kr = kvbase + (size_t)(jb * 64 + row) * (3 * DD) + c0;
            const float* vr = kr + DD;
            #pragma unroll
            for (int j = 0; j < 8; j++) {
                float4 kv = *(const float4*)(kr + j * 4);
                uint4 hi, lo; split4(kv, hi, lo);
                *(uint4*)&KhP[row * KSTR + c0 + j * 4] = hi;
                *(uint4*)&Kl [row * KSTR + c0 + j * 4] = lo;
                float4 vv = *(const float4*)(vr + j * 4);
                uint4 vt;
                vt.x = f2tf(vv.x); vt.y = f2tf(vv.y);
                vt.z = f2tf(vv.z); vt.w = f2tf(vv.w);
                *(uint4*)&Vs[row * VSTR + c0 + j * 4] = vt;
            }
        }
        __syncthreads();

        // ---- S = Q K^T (split-tf32) ----
        float sacc[8][4];
        #pragma unroll
        for (int i = 0; i < 8; i++)
            #pragma unroll
            for (int j = 0; j < 4; j++) sacc[i][j] = 0.f;

        #pragma unroll
        for (int s = 0; s < 8; s++) {
            unsigned ql[4];
            const int qb2 = (warp * 16 + g) * QSTR + s * 8 + tg;
            ql[0] = Ql[qb2];     ql[1] = Ql[qb2 + 8 * QSTR];
            ql[2] = Ql[qb2 + 4]; ql[3] = Ql[qb2 + 8 * QSTR + 4];
            #pragma unroll
            for (int na = 0; na < 8; na++) {
                const int kb = (na * 8 + g) * KSTR + s * 8 + tg;
                const unsigned kh0 = KhP[kb], kh1 = KhP[kb + 4];
                const unsigned kl0 = Kl[kb],  kl1 = Kl[kb + 4];
                mma8(sacc[na], qh[s], kh0, kh1);
                mma8(sacc[na], qh[s], kl0, kl1);
                mma8(sacc[na], ql,    kh0, kh1);
            }
        }

        // ---- online softmax (regs + 4-lane shuffles) ----
        #pragma unroll
        for (int hf = 0; hf < 2; hf++) {
            float rmax = -1e30f;
            #pragma unroll
            for (int na = 0; na < 8; na++)
                rmax = fmaxf(rmax, fmaxf(sacc[na][2*hf], sacc[na][2*hf+1]));
            rmax = fmaxf(rmax, __shfl_xor_sync(0xffffffffu, rmax, 1));
            rmax = fmaxf(rmax, __shfl_xor_sync(0xffffffffu, rmax, 2));
            const float mn = fmaxf(mrow[hf], rmax);
            const float corr = __expf(mrow[hf] - mn);
            mrow[hf] = mn;
            float rs = 0.f;
            #pragma unroll
            for (int na = 0; na < 8; na++) {
                const float e0 = __expf(sacc[na][2*hf]   - mn);
                const float e1 = __expf(sacc[na][2*hf+1] - mn);
                sacc[na][2*hf] = e0; sacc[na][2*hf+1] = e1;
                rs += e0 + e1;
            }
            rs += __shfl_xor_sync(0xffffffffu, rs, 1);
            rs += __shfl_xor_sync(0xffffffffu, rs, 2);
            lrow[hf] = lrow[hf] * corr + rs;
            #pragma unroll
            for (int na = 0; na < 8; na++) {
                oacc[na][2*hf]   *= corr;
                oacc[na][2*hf+1] *= corr;
            }
        }

        __syncthreads();   // all warps done reading K tiles

        // ---- write P (tf32) into KhP ----
        #pragma unroll
        for (int na = 0; na < 8; na++) {
            const int r0 = warp * 16 + g, c = na * 8 + 2 * tg;
            uint2 p0 = make_uint2(f2tf(sacc[na][0]), f2tf(sacc[na][1]));
            uint2 p1 = make_uint2(f2tf(sacc[na][2]), f2tf(sacc[na][3]));
            *(uint2*)&KhP[r0 * KSTR + c] = p0;
            *(uint2*)&KhP[(r0 + 8) * KSTR + c] = p1;
        }
        __syncwarp(0xffffffffu);

        // ---- O += P @ V ----
        #pragma unroll
        for (int s = 0; s < 8; s++) {
            unsigned ap[4];
            const int pb = (warp * 16 + g) * KSTR + s * 8 + tg;
            ap[0] = KhP[pb];     ap[1] = KhP[pb + 8 * KSTR];
            ap[2] = KhP[pb + 4]; ap[3] = KhP[pb + 8 * KSTR + 4];
            #pragma unroll
            for (int na = 0; na < 8; na++) {
                const unsigned v0 = Vs[(s * 8 + tg)     * VSTR + na * 8 + g];
                const unsigned v1 = Vs[(s * 8 + tg + 4) * VSTR + na * 8 + g];
                mma8(oacc[na], ap, v0, v1);
            }
        }
        __syncthreads();   // before next iter overwrites KhP/Kl/Vs
    }

    const float inv0 = 1.0f / lrow[0], inv1 = 1.0f / lrow[1];
    #pragma unroll
    for (int na = 0; na < 8; na++) {
        const int row = qb * 64 + warp * 16 + g;
        const int col = h * HD + na * 8 + 2 * tg;
        float2 w0 = make_float2(oacc[na][0] * inv0, oacc[na][1] * inv0);
        float2 w1 = make_float2(oacc[na][2] * inv1, oacc[na][3] * inv1);
        *(float2*)&g_ctx[((size_t)b * SS + row) * DD + col] = w0;
        *(float2*)&g_ctx[((size_t)b * SS + row + 8) * DD + col] = w1;
    }
}

// ---------------------------------------------------------------------------
extern "C" void kernel_launch(void* const* d_in, const int* in_sizes, int n_in,
                              void* d_out, int out_size)
{
    const float* x     = (const float*)d_in[0];
    const float* w_qkv = (const float*)d_in[1];
    const float* w_out = (const float*)d_in[2];
    const float* b_out = (const float*)d_in[3];
    float* out = (float*)d_out;

    float* qkv_ptr = nullptr;
    float* ctx_ptr = nullptr;
    cudaGetSymbolAddress((void**)&qkv_ptr, g_qkv);
    cudaGetSymbolAddress((void**)&ctx_ptr, g_ctx);

    cudaFuncSetAttribute(attn_tc, cudaFuncAttributeMaxDynamicSharedMemorySize,
                         ATT_SMEM);

    gemm_tc<false><<<dim3(3 * DD / 128, M_TOK / 128), 256>>>(
        x, w_qkv, nullptr, qkv_ptr, M_TOK, 3 * DD, DD);

    attn_tc<<<dim3(SS / 64, BB * HH), 128, ATT_SMEM>>>();

    gemm_tc<true><<<dim3(DD / 128, M_TOK / 128), 256>>>(
        ctx_ptr, w_out, b_out, out, M_TOK, DD, DD);
}

// round 3
// speedup vs baseline: 1.9064x; 1.3814x over previous
#include <cuda_runtime.h>
#include <cuda_bf16.h>
#include <math.h>

#define BB 4
#define SS 2048
#define DD 768
#define HH 12
#define HD 64
#define QK_SCALE 0.125f
#define M_TOK (BB*SS)

__device__ float g_qkv[(size_t)M_TOK * 3 * DD];  // [B,S,3,H,HD]
__device__ float g_ctx[(size_t)M_TOK * DD];      // [B,S,D]

// ---------------- helpers ----------------
__device__ __forceinline__ unsigned f2tf(float x) {
    unsigned r; asm("cvt.rna.tf32.f32 %0, %1;" : "=r"(r) : "f"(x)); return r;
}
__device__ __forceinline__ unsigned short f2bf(float x) {
    return __bfloat16_as_ushort(__float2bfloat16(x));
}
__device__ __forceinline__ float bf2f(unsigned short h) {
    return __bfloat162float(__ushort_as_bfloat16(h));
}
// pack two consecutive real-k values, split into hi/lo bf16x2 words
__device__ __forceinline__ void splitpack(float x0, float x1,
                                          unsigned& whi, unsigned& wlo) {
    unsigned short h0 = f2bf(x0), h1 = f2bf(x1);
    unsigned short l0 = f2bf(x0 - bf2f(h0)), l1 = f2bf(x1 - bf2f(h1));
    whi = (unsigned)h0 | ((unsigned)h1 << 16);
    wlo = (unsigned)l0 | ((unsigned)l1 << 16);
}
__device__ __forceinline__ void mmabf(float c[4], const unsigned a[4],
                                      unsigned b0, unsigned b1) {
    asm volatile(
        "mma.sync.aligned.m16n8k16.row.col.f32.bf16.bf16.f32 "
        "{%0,%1,%2,%3},{%4,%5,%6,%7},{%8,%9},{%0,%1,%2,%3};"
        : "+f"(c[0]), "+f"(c[1]), "+f"(c[2]), "+f"(c[3])
        : "r"(a[0]), "r"(a[1]), "r"(a[2]), "r"(a[3]), "r"(b0), "r"(b1));
}
__device__ __forceinline__ void mma8(float c[4], const unsigned a[4],
                                     unsigned b0, unsigned b1) {
    asm volatile(
        "mma.sync.aligned.m16n8k8.row.col.f32.tf32.tf32.f32 "
        "{%0,%1,%2,%3},{%4,%5,%6,%7},{%8,%9},{%0,%1,%2,%3};"
        : "+f"(c[0]), "+f"(c[1]), "+f"(c[2]), "+f"(c[3])
        : "r"(a[0]), "r"(a[1]), "r"(a[2]), "r"(a[3]), "r"(b0), "r"(b1));
}

// ---------------------------------------------------------------------------
// Dense GEMM, bf16 3-term split, double buffered. 128x128 tile, k-tile 16.
// 8 warps of 64x32. A words: [row][kw] (kw = real-k pair), B words: [kw][n].
// ---------------------------------------------------------------------------
#define ASTRW 12     // 8 words + pad; frag addr g*12+tg conflict-free
#define BSTRW 136    // frag addr tg*136+g conflict-free

template<bool BIAS>
__global__ void __launch_bounds__(256)
gemm_tc(const float* __restrict__ A, const float* __restrict__ Bm,
        const float* __restrict__ bias, float* __restrict__ C,
        int M, int N, int K)
{
    __shared__ unsigned Ahi[2][128 * ASTRW], Alo[2][128 * ASTRW];
    __shared__ unsigned Bhi[2][8 * BSTRW],  Blo[2][8 * BSTRW];

    const int t = threadIdx.x, lane = t & 31, warp = t >> 5;
    const int g = lane >> 2, tg = lane & 3;
    const int m0 = blockIdx.y * 128, n0 = blockIdx.x * 128;
    const int wm = (warp >> 2) * 64, wn = (warp & 3) * 32;

    const int arow = t >> 1, akw = (t & 1) * 4;    // A: row, word offset (4 words = 8 floats)
    const int bkw  = t >> 5, bn0 = (t & 31) * 4;   // B: k-pair row, n offset

    const float* Ap = A + (size_t)(m0 + arow) * K + akw * 2;
    const float* Bp = Bm + (size_t)(bkw * 2) * N + n0 + bn0;

    float ra[8], rb[8];
    {
        float4 v0 = *(const float4*)Ap, v1 = *(const float4*)(Ap + 4);
        ra[0]=v0.x; ra[1]=v0.y; ra[2]=v0.z; ra[3]=v0.w;
        ra[4]=v1.x; ra[5]=v1.y; ra[6]=v1.z; ra[7]=v1.w;
        float4 w0 = *(const float4*)Bp, w1 = *(const float4*)(Bp + N);
        rb[0]=w0.x; rb[1]=w0.y; rb[2]=w0.z; rb[3]=w0.w;
        rb[4]=w1.x; rb[5]=w1.y; rb[6]=w1.z; rb[7]=w1.w;
    }

    float acc[4][4][4];
    #pragma unroll
    for (int i = 0; i < 4; i++)
        #pragma unroll
        for (int j = 0; j < 4; j++)
            #pragma unroll
            for (int k = 0; k < 4; k++) acc[i][j][k] = 0.f;

    // store tile from regs into buffer p
    auto store_tile = [&](int p) {
        unsigned wh[4], wl[4];
        #pragma unroll
        for (int j = 0; j < 4; j++) splitpack(ra[2*j], ra[2*j+1], wh[j], wl[j]);
        *(uint4*)&Ahi[p][arow * ASTRW + akw] = *(uint4*)wh;
        *(uint4*)&Alo[p][arow * ASTRW + akw] = *(uint4*)wl;
        #pragma unroll
        for (int j = 0; j < 4; j++) {
            unsigned short h0 = f2bf(rb[j]),     h1 = f2bf(rb[4+j]);
            unsigned short l0 = f2bf(rb[j]   - bf2f(h0));
            unsigned short l1 = f2bf(rb[4+j] - bf2f(h1));
            wh[j] = (unsigned)h0 | ((unsigned)h1 << 16);
            wl[j] = (unsigned)l0 | ((unsigned)l1 << 16);
        }
        *(uint4*)&Bhi[p][bkw * BSTRW + bn0] = *(uint4*)wh;
        *(uint4*)&Blo[p][bkw * BSTRW + bn0] = *(uint4*)wl;
    };

    store_tile(0);
    __syncthreads();

    const int NT = K / 16;
    for (int kt = 0; kt < NT; kt++) {
        const int cur = kt & 1;
        if (kt + 1 < NT) {   // prefetch next tile into regs
            Ap += 16; Bp += (size_t)16 * N;
            float4 v0 = *(const float4*)Ap, v1 = *(const float4*)(Ap + 4);
            ra[0]=v0.x; ra[1]=v0.y; ra[2]=v0.z; ra[3]=v0.w;
            ra[4]=v1.x; ra[5]=v1.y; ra[6]=v1.z; ra[7]=v1.w;
            float4 w0 = *(const float4*)Bp, w1 = *(const float4*)(Bp + N);
            rb[0]=w0.x; rb[1]=w0.y; rb[2]=w0.z; rb[3]=w0.w;
            rb[4]=w1.x; rb[5]=w1.y; rb[6]=w1.z; rb[7]=w1.w;
        }

        // compute on buffer cur (one k16 chunk)
        unsigned ah[4][4], al[4][4];
        #pragma unroll
        for (int ma = 0; ma < 4; ma++) {
            const int base = (wm + ma * 16 + g) * ASTRW + tg;
            ah[ma][0] = Ahi[cur][base];      ah[ma][1] = Ahi[cur][base + 8 * ASTRW];
            ah[ma][2] = Ahi[cur][base + 4];  ah[ma][3] = Ahi[cur][base + 8 * ASTRW + 4];
            al[ma][0] = Alo[cur][base];      al[ma][1] = Alo[cur][base + 8 * ASTRW];
            al[ma][2] = Alo[cur][base + 4];  al[ma][3] = Alo[cur][base + 8 * ASTRW + 4];
        }
        #pragma unroll
        for (int na = 0; na < 4; na++) {
            const int col = wn + na * 8 + g;
            const unsigned bh0 = Bhi[cur][tg * BSTRW + col];
            const unsigned bh1 = Bhi[cur][(tg + 4) * BSTRW + col];
            const unsigned bl0 = Blo[cur][tg * BSTRW + col];
            const unsigned bl1 = Blo[cur][(tg + 4) * BSTRW + col];
            #pragma unroll
            for (int ma = 0; ma < 4; ma++) {
                mmabf(acc[ma][na], ah[ma], bh0, bh1);
                mmabf(acc[ma][na], ah[ma], bl0, bl1);
                mmabf(acc[ma][na], al[ma], bh0, bh1);
            }
        }

        if (kt + 1 < NT) {
            store_tile(cur ^ 1);
            __syncthreads();
        }
    }

    #pragma unroll
    for (int ma = 0; ma < 4; ma++) {
        #pragma unroll
        for (int na = 0; na < 4; na++) {
            const int row = m0 + wm + ma * 16 + g;
            const int col = n0 + wn + na * 8 + 2 * tg;
            float bx = 0.f, by = 0.f;
            if (BIAS) { bx = bias[col]; by = bias[col + 1]; }
            float2 v0 = make_float2(acc[ma][na][0] + bx, acc[ma][na][1] + by);
            float2 v1 = make_float2(acc[ma][na][2] + bx, acc[ma][na][3] + by);
            *(float2*)&C[(size_t)row * N + col] = v0;
            *(float2*)&C[(size_t)(row + 8) * N + col] = v1;
        }
    }
}

// ---------------------------------------------------------------------------
// Flash attention. 64 q rows per CTA, 4 warps (16 q rows each).
// QK^T: bf16 3-term (Q-hi frags in regs, Q-lo/K-hi/K-lo in smem).
// PV:   single tf32 (P, V rounded to tf32).
// smem words: Qlo[64][36] | Kregion (Khi[32][72], Klo[32][72]; reused as
//             P[64][68] tf32) | V[64][72] tf32 (also Q-hi staging temp).
// ---------------------------------------------------------------------------
#define QSTRW 36
#define KROWW 72
#define VROWW 72
#define PSTRW 68
#define ATT_SMEM ((64*QSTRW + 2*32*KROWW + 64*VROWW) * 4)

__global__ void __launch_bounds__(128, 3)
attn_tc()
{
    extern __shared__ unsigned smu[];
    unsigned* Qlo  = smu;                       // [64][36]
    unsigned* Kreg = smu + 64 * QSTRW;          // Khi | Klo, later P
    unsigned* Khi  = Kreg;
    unsigned* Klo  = Kreg + 32 * KROWW;
    unsigned* Ps   = Kreg;                      // P tf32 [64][68]
    unsigned* Vs   = Kreg + 2 * 32 * KROWW;     // V tf32 [64][72]; Q-hi temp

    const int t = threadIdx.x, lane = t & 31, warp = t >> 5;
    const int g = lane >> 2, tg = lane & 3;
    const int b = blockIdx.y / HH, h = blockIdx.y % HH, qb = blockIdx.x;

    // ---- stage Q: hi -> Vs (temp, stride 36), lo -> Qlo ----
    {
        const int row = t >> 1, d0 = (t & 1) * 32;
        const float* qr = g_qkv + ((size_t)(b * SS + qb * 64 + row)) * (3 * DD)
                        + h * HD + d0;
        #pragma unroll
        for (int j = 0; j < 8; j++) {
            float4 v = *(const float4*)(qr + j * 4);
            v.x *= QK_SCALE; v.y *= QK_SCALE; v.z *= QK_SCALE; v.w *= QK_SCALE;
            unsigned h0, l0, h1, l1;
            splitpack(v.x, v.y, h0, l0);
            splitpack(v.z, v.w, h1, l1);
            const int w0 = d0 / 2 + j * 2;
            Vs [row * QSTRW + w0] = h0;  Vs [row * QSTRW + w0 + 1] = h1;
            Qlo[row * QSTRW + w0] = l0;  Qlo[row * QSTRW + w0 + 1] = l1;
        }
    }
    __syncthreads();
    unsigned qh[4][4];
    #pragma unroll
    for (int c = 0; c < 4; c++) {
        const int base = (warp * 16 + g) * QSTRW + 8 * c + tg;
        qh[c][0] = Vs[base];      qh[c][1] = Vs[base + 8 * QSTRW];
        qh[c][2] = Vs[base + 4];  qh[c][3] = Vs[base + 8 * QSTRW + 4];
    }
    __syncthreads();

    float mrow[2] = {-1e30f, -1e30f}, lrow[2] = {0.f, 0.f};
    float oacc[8][4];
    #pragma unroll
    for (int i = 0; i < 8; i++)
        #pragma unroll
        for (int j = 0; j < 4; j++) oacc[i][j] = 0.f;

    const float* kvbase = g_qkv + ((size_t)b * SS) * (3 * DD) + DD + h * HD;

    for (int jb = 0; jb < SS / 64; jb++) {
        // ---- stage K (bf16 split, word layout [dw][key]) and V (tf32 [key][d]) ----
        {
            const int key = t >> 1, d0 = (t & 1) * 32;
            const float* kr = kvbase + (size_t)(jb * 64 + key) * (3 * DD) + d0;
            const float* vr = kr + DD;
            #pragma unroll
            for (int j = 0; j < 8; j++) {
                float4 kv = *(const float4*)(kr + j * 4);
                unsigned h0, l0, h1, l1;
                splitpack(kv.x, kv.y, h0, l0);
                splitpack(kv.z, kv.w, h1, l1);
                const int dw = d0 / 2 + j * 2;
                Khi[dw * KROWW + key] = h0;  Khi[(dw + 1) * KROWW + key] = h1;
                Klo[dw * KROWW + key] = l0;  Klo[(dw + 1) * KROWW + key] = l1;
                float4 vv = *(const float4*)(vr + j * 4);
                uint4 vt;
                vt.x = f2tf(vv.x); vt.y = f2tf(vv.y);
                vt.z = f2tf(vv.z); vt.w = f2tf(vv.w);
                *(uint4*)&Vs[key * VROWW + d0 + j * 4] = vt;
            }
        }
        __syncthreads();

        // ---- S = Q K^T (bf16 3-term) ----
        float sacc[8][4];
        #pragma unroll
        for (int i = 0; i < 8; i++)
            #pragma unroll
            for (int j = 0; j < 4; j++) sacc[i][j] = 0.f;

        #pragma unroll
        for (int c = 0; c < 4; c++) {
            unsigned ql[4];
            const int qb2 = (warp * 16 + g) * QSTRW + 8 * c + tg;
            ql[0] = Qlo[qb2];      ql[1] = Qlo[qb2 + 8 * QSTRW];
            ql[2] = Qlo[qb2 + 4];  ql[3] = Qlo[qb2 + 8 * QSTRW + 4];
            #pragma unroll
            for (int na = 0; na < 8; na++) {
                const int kc = na * 8 + g;
                const unsigned bh0 = Khi[(8 * c + tg)     * KROWW + kc];
                const unsigned bh1 = Khi[(8 * c + tg + 4) * KROWW + kc];
                const unsigned bl0 = Klo[(8 * c + tg)     * KROWW + kc];
                const unsigned bl1 = Klo[(8 * c + tg + 4) * KROWW + kc];
                mmabf(sacc[na], qh[c], bh0, bh1);
                mmabf(sacc[na], qh[c], bl0, bl1);
                mmabf(sacc[na], ql,    bh0, bh1);
            }
        }

        // ---- online softmax ----
        #pragma unroll
        for (int hf = 0; hf < 2; hf++) {
            float rmax = -1e30f;
            #pragma unroll
            for (int na = 0; na < 8; na++)
                rmax = fmaxf(rmax, fmaxf(sacc[na][2*hf], sacc[na][2*hf+1]));
            rmax = fmaxf(rmax, __shfl_xor_sync(0xffffffffu, rmax, 1));
            rmax = fmaxf(rmax, __shfl_xor_sync(0xffffffffu, rmax, 2));
            const float mn = fmaxf(mrow[hf], rmax);
            const float corr = __expf(mrow[hf] - mn);
            mrow[hf] = mn;
            float rs = 0.f;
            #pragma unroll
            for (int na = 0; na < 8; na++) {
                const float e0 = __expf(sacc[na][2*hf]   - mn);
                const float e1 = __expf(sacc[na][2*hf+1] - mn);
                sacc[na][2*hf] = e0; sacc[na][2*hf+1] = e1;
                rs += e0 + e1;
            }
            rs += __shfl_xor_sync(0xffffffffu, rs, 1);
            rs += __shfl_xor_sync(0xffffffffu, rs, 2);
            lrow[hf] = lrow[hf] * corr + rs;
            #pragma unroll
            for (int na = 0; na < 8; na++) {
                oacc[na][2*hf]   *= corr;
                oacc[na][2*hf+1] *= corr;
            }
        }

        __syncthreads();   // all warps done reading K region

        // ---- write P (tf32) into K region ----
        #pragma unroll
        for (int na = 0; na < 8; na++) {
            const int r0 = warp * 16 + g, c = na * 8 + 2 * tg;
            uint2 p0 = make_uint2(f2tf(sacc[na][0]), f2tf(sacc[na][1]));
            uint2 p1 = make_uint2(f2tf(sacc[na][2]), f2tf(sacc[na][3]));
            *(uint2*)&Ps[r0 * PSTRW + c] = p0;
            *(uint2*)&Ps[(r0 + 8) * PSTRW + c] = p1;
        }
        __syncwarp(0xffffffffu);

        // ---- O += P @ V (tf32) ----
        #pragma unroll
        for (int s = 0; s < 8; s++) {
            unsigned ap[4];
            const int pb = (warp * 16 + g) * PSTRW + s * 8 + tg;
            ap[0] = Ps[pb];      ap[1] = Ps[pb + 8 * PSTRW];
            ap[2] = Ps[pb + 4];  ap[3] = Ps[pb + 8 * PSTRW + 4];
            #pragma unroll
            for (int na = 0; na < 8; na++) {
                const unsigned v0 = Vs[(s * 8 + tg)     * VROWW + na * 8 + g];
                const unsigned v1 = Vs[(s * 8 + tg + 4) * VROWW + na * 8 + g];
                mma8(oacc[na], ap, v0, v1);
            }
        }
        __syncthreads();   // before next iter overwrites K/V/P regions
    }

    const float inv0 = 1.0f / lrow[0], inv1 = 1.0f / lrow[1];
    #pragma unroll
    for (int na = 0; na < 8; na++) {
        const int row = qb * 64 + warp * 16 + g;
        const int col = h * HD + na * 8 + 2 * tg;
        float2 w0 = make_float2(oacc[na][0] * inv0, oacc[na][1] * inv0);
        float2 w1 = make_float2(oacc[na][2] * inv1, oacc[na][3] * inv1);
        *(float2*)&g_ctx[((size_t)b * SS + row) * DD + col] = w0;
        *(float2*)&g_ctx[((size_t)b * SS + row + 8) * DD + col] = w1;
    }
}

// ---------------------------------------------------------------------------
extern "C" void kernel_launch(void* const* d_in, const int* in_sizes, int n_in,
                              void* d_out, int out_size)
{
    const float* x     = (const float*)d_in[0];
    const float* w_qkv = (const float*)d_in[1];
    const float* w_out = (const float*)d_in[2];
    const float* b_out = (const float*)d_in[3];
    float* out = (float*)d_out;

    float* qkv_ptr = nullptr;
    float* ctx_ptr = nullptr;
    cudaGetSymbolAddress((void**)&qkv_ptr, g_qkv);
    cudaGetSymbolAddress((void**)&ctx_ptr, g_ctx);

    cudaFuncSetAttribute(attn_tc, cudaFuncAttributeMaxDynamicSharedMemorySize,
                         ATT_SMEM);

    gemm_tc<false><<<dim3(3 * DD / 128, M_TOK / 128), 256>>>(
        x, w_qkv, nullptr, qkv_ptr, M_TOK, 3 * DD, DD);

    attn_tc<<<dim3(SS / 64, BB * HH), 128, ATT_SMEM>>>();

    gemm_tc<true><<<dim3(DD / 128, M_TOK / 128), 256>>>(
        ctx_ptr, w_out, b_out, out, M_TOK, DD, DD);
}

// round 4
// speedup vs baseline: 2.5973x; 1.3624x over previous
#include <cuda_runtime.h>
#include <cuda_bf16.h>
#include <math.h>

#define BB 4
#define SS 2048
#define DD 768
#define HH 12
#define HD 64
#define QK_SCALE 0.125f
#define M_TOK (BB*SS)

__device__ float g_qkv[(size_t)M_TOK * 3 * DD];  // [B,S,3,H,HD]
__device__ float g_ctx[(size_t)M_TOK * DD];      // [B,S,D]

// ---------------- helpers ----------------
__device__ __forceinline__ unsigned f2tf(float x) {
    unsigned r; asm("cvt.rna.tf32.f32 %0, %1;" : "=r"(r) : "f"(x)); return r;
}
__device__ __forceinline__ unsigned short f2bf(float x) {
    return __bfloat16_as_ushort(__float2bfloat16(x));
}
__device__ __forceinline__ float bf2f(unsigned short h) {
    return __bfloat162float(__ushort_as_bfloat16(h));
}
__device__ __forceinline__ void splitpack(float x0, float x1,
                                          unsigned& whi, unsigned& wlo) {
    unsigned short h0 = f2bf(x0), h1 = f2bf(x1);
    unsigned short l0 = f2bf(x0 - bf2f(h0)), l1 = f2bf(x1 - bf2f(h1));
    whi = (unsigned)h0 | ((unsigned)h1 << 16);
    wlo = (unsigned)l0 | ((unsigned)l1 << 16);
}
__device__ __forceinline__ void mmabf(float c[4], const unsigned a[4],
                                      unsigned b0, unsigned b1) {
    asm volatile(
        "mma.sync.aligned.m16n8k16.row.col.f32.bf16.bf16.f32 "
        "{%0,%1,%2,%3},{%4,%5,%6,%7},{%8,%9},{%0,%1,%2,%3};"
        : "+f"(c[0]), "+f"(c[1]), "+f"(c[2]), "+f"(c[3])
        : "r"(a[0]), "r"(a[1]), "r"(a[2]), "r"(a[3]), "r"(b0), "r"(b1));
}
__device__ __forceinline__ void mma8(float c[4], const unsigned a[4],
                                     unsigned b0, unsigned b1) {
    asm volatile(
        "mma.sync.aligned.m16n8k8.row.col.f32.tf32.tf32.f32 "
        "{%0,%1,%2,%3},{%4,%5,%6,%7},{%8,%9},{%0,%1,%2,%3};"
        : "+f"(c[0]), "+f"(c[1]), "+f"(c[2]), "+f"(c[3])
        : "r"(a[0]), "r"(a[1]), "r"(a[2]), "r"(a[3]), "r"(b0), "r"(b1));
}
__device__ __forceinline__ void cp16(unsigned dst, const void* src) {
    asm volatile("cp.async.cg.shared.global [%0], [%1], 16;"
                 :: "r"(dst), "l"(src));
}
__device__ __forceinline__ void cp_commit() {
    asm volatile("cp.async.commit_group;");
}

// ---------------------------------------------------------------------------
// Dense GEMM, bf16 3-term split, double buffered, 2 CTAs/SM.
// ---------------------------------------------------------------------------
#define ASTRW 12
#define BSTRW 136

template<bool BIAS>
__global__ void __launch_bounds__(256, 2)
gemm_tc(const float* __restrict__ A, const float* __restrict__ Bm,
        const float* __restrict__ bias, float* __restrict__ C,
        int M, int N, int K)
{
    __shared__ unsigned Ahi[2][128 * ASTRW], Alo[2][128 * ASTRW];
    __shared__ unsigned Bhi[2][8 * BSTRW],  Blo[2][8 * BSTRW];

    const int t = threadIdx.x, lane = t & 31, warp = t >> 5;
    const int g = lane >> 2, tg = lane & 3;
    const int m0 = blockIdx.y * 128, n0 = blockIdx.x * 128;
    const int wm = (warp >> 2) * 64, wn = (warp & 3) * 32;

    const int arow = t >> 1, akw = (t & 1) * 4;
    const int bkw  = t >> 5, bn0 = (t & 31) * 4;

    const float* Ap = A + (size_t)(m0 + arow) * K + akw * 2;
    const float* Bp = Bm + (size_t)(bkw * 2) * N + n0 + bn0;

    float ra[8], rb[8];
    {
        float4 v0 = *(const float4*)Ap, v1 = *(const float4*)(Ap + 4);
        ra[0]=v0.x; ra[1]=v0.y; ra[2]=v0.z; ra[3]=v0.w;
        ra[4]=v1.x; ra[5]=v1.y; ra[6]=v1.z; ra[7]=v1.w;
        float4 w0 = *(const float4*)Bp, w1 = *(const float4*)(Bp + N);
        rb[0]=w0.x; rb[1]=w0.y; rb[2]=w0.z; rb[3]=w0.w;
        rb[4]=w1.x; rb[5]=w1.y; rb[6]=w1.z; rb[7]=w1.w;
    }

    float acc[4][4][4];
    #pragma unroll
    for (int i = 0; i < 4; i++)
        #pragma unroll
        for (int j = 0; j < 4; j++)
            #pragma unroll
            for (int k = 0; k < 4; k++) acc[i][j][k] = 0.f;

    auto store_tile = [&](int p) {
        unsigned wh[4], wl[4];
        #pragma unroll
        for (int j = 0; j < 4; j++) splitpack(ra[2*j], ra[2*j+1], wh[j], wl[j]);
        *(uint4*)&Ahi[p][arow * ASTRW + akw] = *(uint4*)wh;
        *(uint4*)&Alo[p][arow * ASTRW + akw] = *(uint4*)wl;
        #pragma unroll
        for (int j = 0; j < 4; j++) {
            unsigned short h0 = f2bf(rb[j]),     h1 = f2bf(rb[4+j]);
            unsigned short l0 = f2bf(rb[j]   - bf2f(h0));
            unsigned short l1 = f2bf(rb[4+j] - bf2f(h1));
            wh[j] = (unsigned)h0 | ((unsigned)h1 << 16);
            wl[j] = (unsigned)l0 | ((unsigned)l1 << 16);
        }
        *(uint4*)&Bhi[p][bkw * BSTRW + bn0] = *(uint4*)wh;
        *(uint4*)&Blo[p][bkw * BSTRW + bn0] = *(uint4*)wl;
    };

    store_tile(0);
    __syncthreads();

    const int NT = K / 16;
    for (int kt = 0; kt < NT; kt++) {
        const int cur = kt & 1;
        if (kt + 1 < NT) {
            Ap += 16; Bp += (size_t)16 * N;
            float4 v0 = *(const float4*)Ap, v1 = *(const float4*)(Ap + 4);
            ra[0]=v0.x; ra[1]=v0.y; ra[2]=v0.z; ra[3]=v0.w;
            ra[4]=v1.x; ra[5]=v1.y; ra[6]=v1.z; ra[7]=v1.w;
            float4 w0 = *(const float4*)Bp, w1 = *(const float4*)(Bp + N);
            rb[0]=w0.x; rb[1]=w0.y; rb[2]=w0.z; rb[3]=w0.w;
            rb[4]=w1.x; rb[5]=w1.y; rb[6]=w1.z; rb[7]=w1.w;
        }

        unsigned ah[4][4], al[4][4];
        #pragma unroll
        for (int ma = 0; ma < 4; ma++) {
            const int base = (wm + ma * 16 + g) * ASTRW + tg;
            ah[ma][0] = Ahi[cur][base];      ah[ma][1] = Ahi[cur][base + 8 * ASTRW];
            ah[ma][2] = Ahi[cur][base + 4];  ah[ma][3] = Ahi[cur][base + 8 * ASTRW + 4];
            al[ma][0] = Alo[cur][base];      al[ma][1] = Alo[cur][base + 8 * ASTRW];
            al[ma][2] = Alo[cur][base + 4];  al[ma][3] = Alo[cur][base + 8 * ASTRW + 4];
        }
        #pragma unroll
        for (int na = 0; na < 4; na++) {
            const int col = wn + na * 8 + g;
            const unsigned bh0 = Bhi[cur][tg * BSTRW + col];
            const unsigned bh1 = Bhi[cur][(tg + 4) * BSTRW + col];
            const unsigned bl0 = Blo[cur][tg * BSTRW + col];
            const unsigned bl1 = Blo[cur][(tg + 4) * BSTRW + col];
            #pragma unroll
            for (int ma = 0; ma < 4; ma++) {
                mmabf(acc[ma][na], ah[ma], bh0, bh1);
                mmabf(acc[ma][na], ah[ma], bl0, bl1);
                mmabf(acc[ma][na], al[ma], bh0, bh1);
            }
        }

        if (kt + 1 < NT) {
            store_tile(cur ^ 1);
            __syncthreads();
        }
    }

    #pragma unroll
    for (int ma = 0; ma < 4; ma++) {
        #pragma unroll
        for (int na = 0; na < 4; na++) {
            const int row = m0 + wm + ma * 16 + g;
            const int col = n0 + wn + na * 8 + 2 * tg;
            float bx = 0.f, by = 0.f;
            if (BIAS) { bx = bias[col]; by = bias[col + 1]; }
            float2 v0 = make_float2(acc[ma][na][0] + bx, acc[ma][na][1] + by);
            float2 v1 = make_float2(acc[ma][na][2] + bx, acc[ma][na][3] + by);
            *(float2*)&C[(size_t)row * N + col] = v0;
            *(float2*)&C[(size_t)(row + 8) * N + col] = v1;
        }
    }
}

// ---------------------------------------------------------------------------
// Flash attention v2: Mq=128 per CTA, 256 threads (8 warps x 16 q rows).
// K prefetched in regs (split to bf16 at store); V via cp.async double buffer,
// consumed as truncated tf32. P never touches smem: tf32 A-frags built from
// S-accumulator fragments via intra-warp shuffles.
// ---------------------------------------------------------------------------
#define QSTRW 36
#define KROWW 72
#define VROWW 72
#define ATT_SMEM ((128*QSTRW + 2*32*KROWW + 2*64*VROWW) * 4)   // 73728 B

__global__ void __launch_bounds__(256, 2)
attn_tc()
{
    extern __shared__ unsigned smu[];
    unsigned* Qlo = smu;                        // [128][36]
    unsigned* Khi = smu + 128 * QSTRW;          // [32][72]
    unsigned* Klo = Khi + 32 * KROWW;           // [32][72]
    unsigned* V0  = Klo + 32 * KROWW;           // [64][72] raw fp32
    unsigned* V1  = V0 + 64 * VROWW;            // [64][72]; Q-hi temp at start

    const int t = threadIdx.x, lane = t & 31, warp = t >> 5;
    const int g = lane >> 2, tg = lane & 3;
    const int b = blockIdx.y / HH, h = blockIdx.y % HH, qb = blockIdx.x;

    // ---- stage Q: hi -> V1 (temp), lo -> Qlo ----
    {
        const int row = t & 127, c0 = (t >> 7) * 32;
        const float* qr = g_qkv + ((size_t)(b * SS + qb * 128 + row)) * (3 * DD)
                        + h * HD + c0;
        #pragma unroll
        for (int j = 0; j < 8; j++) {
            float4 v = *(const float4*)(qr + j * 4);
            v.x *= QK_SCALE; v.y *= QK_SCALE; v.z *= QK_SCALE; v.w *= QK_SCALE;
            unsigned h0, l0, h1, l1;
            splitpack(v.x, v.y, h0, l0);
            splitpack(v.z, v.w, h1, l1);
            const int w0 = c0 / 2 + j * 2;
            V1 [row * QSTRW + w0] = h0;  V1 [row * QSTRW + w0 + 1] = h1;
            Qlo[row * QSTRW + w0] = l0;  Qlo[row * QSTRW + w0 + 1] = l1;
        }
    }

    const float* kvbase = g_qkv + ((size_t)b * SS) * (3 * DD) + DD + h * HD;
    const int key = t & 63, dp = t >> 6;    // staging role: key row, d-chunk

    // prefetch K block 0 into regs; cp.async V block 0 -> V0
    float rk[16];
    {
        const float* kr = kvbase + (size_t)key * (3 * DD) + dp * 16;
        #pragma unroll
        for (int i = 0; i < 4; i++) *(float4*)&rk[4*i] = *(const float4*)(kr + 4*i);
        unsigned vdst = (unsigned)__cvta_generic_to_shared(&V0[key * VROWW + dp * 16]);
        const float* vr = kr + DD;
        #pragma unroll
        for (int i = 0; i < 4; i++) cp16(vdst + 16 * i, vr + 4 * i);
        cp_commit();
    }
    __syncthreads();

    // Q-hi fragments from V1 temp
    unsigned qh[4][4];
    #pragma unroll
    for (int c = 0; c < 4; c++) {
        const int base = (warp * 16 + g) * QSTRW + 8 * c + tg;
        qh[c][0] = V1[base];      qh[c][1] = V1[base + 8 * QSTRW];
        qh[c][2] = V1[base + 4];  qh[c][3] = V1[base + 8 * QSTRW + 4];
    }

    float mrow[2] = {-1e30f, -1e30f}, lrow[2] = {0.f, 0.f};
    float oacc[8][4];
    #pragma unroll
    for (int i = 0; i < 8; i++)
        #pragma unroll
        for (int j = 0; j < 4; j++) oacc[i][j] = 0.f;

    const int src1 = (lane & 28) | (tg >> 1);
    const int src2 = src1 + 2;
    const bool odd = tg & 1;

    const int NT = SS / 64;
    for (int jb = 0; jb < NT; jb++) {
        __syncthreads();   // prev compute done with Khi/Klo/V[cur]; qh reads done (jb=0)

        // store K split (regs -> smem), layout [dw][key]
        #pragma unroll
        for (int j = 0; j < 8; j++) {
            unsigned hw, lw;
            splitpack(rk[2*j], rk[2*j+1], hw, lw);
            const int dw = dp * 8 + j;
            Khi[dw * KROWW + key] = hw;
            Klo[dw * KROWW + key] = lw;
        }

        if (jb + 1 < NT) {
            const float* kr = kvbase + (size_t)((jb + 1) * 64 + key) * (3 * DD) + dp * 16;
            #pragma unroll
            for (int i = 0; i < 4; i++) *(float4*)&rk[4*i] = *(const float4*)(kr + 4*i);
            unsigned* Vnxt = ((jb + 1) & 1) ? V1 : V0;
            unsigned vdst = (unsigned)__cvta_generic_to_shared(&Vnxt[key * VROWW + dp * 16]);
            const float* vr = kr + DD;
            #pragma unroll
            for (int i = 0; i < 4; i++) cp16(vdst + 16 * i, vr + 4 * i);
            cp_commit();
            asm volatile("cp.async.wait_group 1;");
        } else {
            asm volatile("cp.async.wait_group 0;");
        }
        __syncthreads();   // K smem + V(jb) visible to all

        const unsigned* Vs = (jb & 1) ? V1 : V0;

        // ---- S = Q K^T (bf16 3-term) ----
        float sacc[8][4];
        #pragma unroll
        for (int i = 0; i < 8; i++)
            #pragma unroll
            for (int j = 0; j < 4; j++) sacc[i][j] = 0.f;

        #pragma unroll
        for (int c = 0; c < 4; c++) {
            unsigned ql[4];
            const int qb2 = (warp * 16 + g) * QSTRW + 8 * c + tg;
            ql[0] = Qlo[qb2];      ql[1] = Qlo[qb2 + 8 * QSTRW];
            ql[2] = Qlo[qb2 + 4];  ql[3] = Qlo[qb2 + 8 * QSTRW + 4];
            #pragma unroll
            for (int na = 0; na < 8; na++) {
                const int kc = na * 8 + g;
                const unsigned bh0 = Khi[(8 * c + tg)     * KROWW + kc];
                const unsigned bh1 = Khi[(8 * c + tg + 4) * KROWW + kc];
                const unsigned bl0 = Klo[(8 * c + tg)     * KROWW + kc];
                const unsigned bl1 = Klo[(8 * c + tg + 4) * KROWW + kc];
                mmabf(sacc[na], qh[c], bh0, bh1);
                mmabf(sacc[na], qh[c], bl0, bl1);
                mmabf(sacc[na], ql,    bh0, bh1);
            }
        }

        // ---- online softmax ----
        #pragma unroll
        for (int hf = 0; hf < 2; hf++) {
            float rmax = -1e30f;
            #pragma unroll
            for (int na = 0; na < 8; na++)
                rmax = fmaxf(rmax, fmaxf(sacc[na][2*hf], sacc[na][2*hf+1]));
            rmax = fmaxf(rmax, __shfl_xor_sync(0xffffffffu, rmax, 1));
            rmax = fmaxf(rmax, __shfl_xor_sync(0xffffffffu, rmax, 2));
            const float mn = fmaxf(mrow[hf], rmax);
            const float corr = __expf(mrow[hf] - mn);
            mrow[hf] = mn;
            float rs = 0.f;
            #pragma unroll
            for (int na = 0; na < 8; na++) {
                const float e0 = __expf(sacc[na][2*hf]   - mn);
                const float e1 = __expf(sacc[na][2*hf+1] - mn);
                sacc[na][2*hf] = e0; sacc[na][2*hf+1] = e1;
                rs += e0 + e1;
            }
            rs += __shfl_xor_sync(0xffffffffu, rs, 1);
            rs += __shfl_xor_sync(0xffffffffu, rs, 2);
            lrow[hf] = lrow[hf] * corr + rs;
            #pragma unroll
            for (int na = 0; na < 8; na++) {
                oacc[na][2*hf]   *= corr;
                oacc[na][2*hf+1] *= corr;
            }
        }

        // ---- O += P @ V : P tf32 A-frags built via shuffles ----
        #pragma unroll
        for (int s = 0; s < 8; s++) {
            const float e0 = __shfl_sync(0xffffffffu, sacc[s][0], src1);
            const float e1 = __shfl_sync(0xffffffffu, sacc[s][1], src1);
            const float e2 = __shfl_sync(0xffffffffu, sacc[s][2], src1);
            const float e3 = __shfl_sync(0xffffffffu, sacc[s][3], src1);
            const float f0 = __shfl_sync(0xffffffffu, sacc[s][0], src2);
            const float f1 = __shfl_sync(0xffffffffu, sacc[s][1], src2);
            const float f2 = __shfl_sync(0xffffffffu, sacc[s][2], src2);
            const float f3 = __shfl_sync(0xffffffffu, sacc[s][3], src2);
            unsigned ap[4];
            ap[0] = f2tf(odd ? e1 : e0);
            ap[1] = f2tf(odd ? e3 : e2);
            ap[2] = f2tf(odd ? f1 : f0);
            ap[3] = f2tf(odd ? f3 : f2);
            #pragma unroll
            for (int na = 0; na < 8; na++) {
                const unsigned v0 = Vs[(s * 8 + tg)     * VROWW + na * 8 + g];
                const unsigned v1 = Vs[(s * 8 + tg + 4) * VROWW + na * 8 + g];
                mma8(oacc[na], ap, v0, v1);
            }
        }
    }

    const float inv0 = 1.0f / lrow[0], inv1 = 1.0f / lrow[1];
    #pragma unroll
    for (int na = 0; na < 8; na++) {
        const int row = qb * 128 + warp * 16 + g;
        const int col = h * HD + na * 8 + 2 * tg;
        float2 w0 = make_float2(oacc[na][0] * inv0, oacc[na][1] * inv0);
        float2 w1 = make_float2(oacc[na][2] * inv1, oacc[na][3] * inv1);
        *(float2*)&g_ctx[((size_t)b * SS + row) * DD + col] = w0;
        *(float2*)&g_ctx[((size_t)b * SS + row + 8) * DD + col] = w1;
    }
}

// ---------------------------------------------------------------------------
extern "C" void kernel_launch(void* const* d_in, const int* in_sizes, int n_in,
                              void* d_out, int out_size)
{
    const float* x     = (const float*)d_in[0];
    const float* w_qkv = (const float*)d_in[1];
    const float* w_out = (const float*)d_in[2];
    const float* b_out = (const float*)d_in[3];
    float* out = (float*)d_out;

    float* qkv_ptr = nullptr;
    float* ctx_ptr = nullptr;
    cudaGetSymbolAddress((void**)&qkv_ptr, g_qkv);
    cudaGetSymbolAddress((void**)&ctx_ptr, g_ctx);

    cudaFuncSetAttribute(attn_tc, cudaFuncAttributeMaxDynamicSharedMemorySize,
                         ATT_SMEM);

    gemm_tc<false><<<dim3(3 * DD / 128, M_TOK / 128), 256>>>(
        x, w_qkv, nullptr, qkv_ptr, M_TOK, 3 * DD, DD);

    attn_tc<<<dim3(SS / 128, BB * HH), 256, ATT_SMEM>>>();

    gemm_tc<true><<<dim3(DD / 128, M_TOK / 128), 256>>>(
        ctx_ptr, w_out, b_out, out, M_TOK, DD, DD);
}

// round 5
// speedup vs baseline: 3.1062x; 1.1959x over previous
#include <cuda_runtime.h>
#include <cuda_bf16.h>
#include <math.h>

#define BB 4
#define SS 2048
#define DD 768
#define HH 12
#define HD 64
#define QK_SCALE 0.125f
#define M_TOK (BB*SS)          // 8192
#define KW_D (DD/2)            // 384 words per 768 k
#define N_QKV (3*DD)           // 2304

// ---------------- prepacked global scratch ----------------
__device__ unsigned g_xhi[(size_t)M_TOK * KW_D], g_xlo[(size_t)M_TOK * KW_D];
__device__ unsigned g_wqhi[(size_t)KW_D * N_QKV], g_wqlo[(size_t)KW_D * N_QKV];
__device__ unsigned g_wohi[(size_t)KW_D * DD],   g_wolo[(size_t)KW_D * DD];
__device__ unsigned g_qhi[(size_t)M_TOK * KW_D], g_qlo[(size_t)M_TOK * KW_D];
__device__ unsigned g_khi[(size_t)BB*HH*32*SS],  g_klo[(size_t)BB*HH*32*SS];
__device__ float    g_v  [(size_t)BB*HH*SS*HD];
__device__ unsigned g_chi[(size_t)M_TOK * KW_D], g_clo[(size_t)M_TOK * KW_D];

// ---------------- helpers ----------------
__device__ __forceinline__ unsigned f2tf(float x) {
    unsigned r; asm("cvt.rna.tf32.f32 %0, %1;" : "=r"(r) : "f"(x)); return r;
}
__device__ __forceinline__ unsigned short f2bf(float x) {
    return __bfloat16_as_ushort(__float2bfloat16(x));
}
__device__ __forceinline__ float bf2f(unsigned short h) {
    return __bfloat162float(__ushort_as_bfloat16(h));
}
__device__ __forceinline__ void splitpack(float x0, float x1,
                                          unsigned& whi, unsigned& wlo) {
    unsigned short h0 = f2bf(x0), h1 = f2bf(x1);
    unsigned short l0 = f2bf(x0 - bf2f(h0)), l1 = f2bf(x1 - bf2f(h1));
    whi = (unsigned)h0 | ((unsigned)h1 << 16);
    wlo = (unsigned)l0 | ((unsigned)l1 << 16);
}
__device__ __forceinline__ void mmabf(float c[4], const unsigned a[4],
                                      unsigned b0, unsigned b1) {
    asm volatile(
        "mma.sync.aligned.m16n8k16.row.col.f32.bf16.bf16.f32 "
        "{%0,%1,%2,%3},{%4,%5,%6,%7},{%8,%9},{%0,%1,%2,%3};"
        : "+f"(c[0]), "+f"(c[1]), "+f"(c[2]), "+f"(c[3])
        : "r"(a[0]), "r"(a[1]), "r"(a[2]), "r"(a[3]), "r"(b0), "r"(b1));
}
__device__ __forceinline__ void mma8(float c[4], const unsigned a[4],
                                     unsigned b0, unsigned b1) {
    asm volatile(
        "mma.sync.aligned.m16n8k8.row.col.f32.tf32.tf32.f32 "
        "{%0,%1,%2,%3},{%4,%5,%6,%7},{%8,%9},{%0,%1,%2,%3};"
        : "+f"(c[0]), "+f"(c[1]), "+f"(c[2]), "+f"(c[3])
        : "r"(a[0]), "r"(a[1]), "r"(a[2]), "r"(a[3]), "r"(b0), "r"(b1));
}
__device__ __forceinline__ void cp16(unsigned dst, const void* src) {
    asm volatile("cp.async.cg.shared.global [%0], [%1], 16;"
                 :: "r"(dst), "l"(src));
}
__device__ __forceinline__ void cp_commit() {
    asm volatile("cp.async.commit_group;");
}

// ---------------- convert kernels ----------------
__global__ void conv_A(const float* __restrict__ in, unsigned* __restrict__ hi,
                       unsigned* __restrict__ lo, int nwords)
{
    int i = blockIdx.x * blockDim.x + threadIdx.x;
    if (i < nwords) {
        float2 v = ((const float2*)in)[i];
        unsigned h, l; splitpack(v.x, v.y, h, l);
        hi[i] = h; lo[i] = l;
    }
}
// B layout: word[kw][n] = pack(in[2kw][n], in[2kw+1][n])
__global__ void conv_B(const float* __restrict__ in, unsigned* __restrict__ hi,
                       unsigned* __restrict__ lo, int KWr, int N)
{
    int i = blockIdx.x * blockDim.x + threadIdx.x;
    if (i < KWr * N) {
        int kw = i / N, n = i - kw * N;
        unsigned h, l;
        splitpack(in[(size_t)(2*kw) * N + n], in[(size_t)(2*kw+1) * N + n], h, l);
        hi[i] = h; lo[i] = l;
    }
}

// ---------------------------------------------------------------------------
// Packed-operand GEMM: 128x128 tile, k-tile 16 (8 words), 3-stage cp.async.
// A words [M][KW], B words [KW][N]. EPI: 0 = fp32 C + bias, 1 = QKV routing.
// ---------------------------------------------------------------------------
#define GAS 12            // A smem row stride (8 data + 4 pad words)
#define GBS 136           // B smem row stride (128 data + 8 pad words)
#define STW 5248          // words per stage: 2*128*12 + 2*8*136
#define GEMM_SMEM (3 * STW * 4)

template<int EPI>
__global__ void __launch_bounds__(256, 2)
gemm_pk(const unsigned* __restrict__ Ahi_g, const unsigned* __restrict__ Alo_g,
        const unsigned* __restrict__ Bhi_g, const unsigned* __restrict__ Blo_g,
        const float* __restrict__ bias, float* __restrict__ C,
        int KWr, int Nn)
{
    extern __shared__ unsigned smw[];
    const unsigned smb = (unsigned)__cvta_generic_to_shared(smw);

    const int t = threadIdx.x, lane = t & 31, warp = t >> 5;
    const int g = lane >> 2, tg = lane & 3;
    const int m0 = blockIdx.y * 128, n0 = blockIdx.x * 128;
    const int wm = (warp >> 2) * 64, wn = (warp & 3) * 32;

    const int arow = t >> 1, ahalf = t & 1;       // A: 128 rows x 2 chunks
    const int bkw = t >> 5, bc = (t & 31) * 4;    // B: 8 kw rows x 32 chunks

    const int NT = KWr / 8;

    auto issue = [&](int kt) {
        if (kt < NT) {
            const unsigned sa = smb + (unsigned)(kt % 3) * STW * 4;
            const size_t aoff = (size_t)(m0 + arow) * KWr + kt * 8 + ahalf * 4;
            cp16(sa + (arow * GAS + ahalf * 4) * 4,            Ahi_g + aoff);
            cp16(sa + (1536 + arow * GAS + ahalf * 4) * 4,     Alo_g + aoff);
            const size_t boff = (size_t)(kt * 8 + bkw) * Nn + n0 + bc;
            cp16(sa + (3072 + bkw * GBS + bc) * 4,             Bhi_g + boff);
            cp16(sa + (4160 + bkw * GBS + bc) * 4,             Blo_g + boff);
        }
        cp_commit();
    };

    float acc[4][4][4];
    #pragma unroll
    for (int i = 0; i < 4; i++)
        #pragma unroll
        for (int j = 0; j < 4; j++)
            #pragma unroll
            for (int k = 0; k < 4; k++) acc[i][j][k] = 0.f;

    issue(0); issue(1);

    for (int kt = 0; kt < NT; kt++) {
        asm volatile("cp.async.wait_group 1;");
        __syncthreads();
        issue(kt + 2);

        const unsigned* SA_hi = smw + (kt % 3) * STW;
        const unsigned* SA_lo = SA_hi + 1536;
        const unsigned* SB_hi = SA_hi + 3072;
        const unsigned* SB_lo = SA_hi + 4160;

        unsigned ah[4][4], al[4][4];
        #pragma unroll
        for (int ma = 0; ma < 4; ma++) {
            const int base = (wm + ma * 16 + g) * GAS + tg;
            ah[ma][0] = SA_hi[base];      ah[ma][1] = SA_hi[base + 8 * GAS];
            ah[ma][2] = SA_hi[base + 4];  ah[ma][3] = SA_hi[base + 8 * GAS + 4];
            al[ma][0] = SA_lo[base];      al[ma][1] = SA_lo[base + 8 * GAS];
            al[ma][2] = SA_lo[base + 4];  al[ma][3] = SA_lo[base + 8 * GAS + 4];
        }
        #pragma unroll
        for (int na = 0; na < 4; na++) {
            const int col = wn + na * 8 + g;
            const unsigned bh0 = SB_hi[tg * GBS + col];
            const unsigned bh1 = SB_hi[(tg + 4) * GBS + col];
            const unsigned bl0 = SB_lo[tg * GBS + col];
            const unsigned bl1 = SB_lo[(tg + 4) * GBS + col];
            #pragma unroll
            for (int ma = 0; ma < 4; ma++) {
                mmabf(acc[ma][na], ah[ma], bh0, bh1);
                mmabf(acc[ma][na], ah[ma], bl0, bl1);
                mmabf(acc[ma][na], al[ma], bh0, bh1);
            }
        }
    }

    if (EPI == 0) {
        #pragma unroll
        for (int ma = 0; ma < 4; ma++) {
            #pragma unroll
            for (int na = 0; na < 4; na++) {
                const int row = m0 + wm + ma * 16 + g;
                const int col = n0 + wn + na * 8 + 2 * tg;
                const float bx = bias[col], by = bias[col + 1];
                float2 v0 = make_float2(acc[ma][na][0] + bx, acc[ma][na][1] + by);
                float2 v1 = make_float2(acc[ma][na][2] + bx, acc[ma][na][3] + by);
                *(float2*)&C[(size_t)row * Nn + col] = v0;
                *(float2*)&C[(size_t)(row + 8) * Nn + col] = v1;
            }
        }
    } else {
        // QKV routing epilogue (whole CTA sits in one of Q/K/V sections)
        #pragma unroll
        for (int na = 0; na < 4; na++) {
            const int col = n0 + wn + na * 8 + 2 * tg;
            const int sec = col / DD;
            const int within = col - sec * DD;
            const int h = within >> 6, hd = within & 63;
            #pragma unroll
            for (int ma = 0; ma < 4; ma++) {
                const int r0 = m0 + wm + ma * 16 + g;
                const float a0 = acc[ma][na][0], a1 = acc[ma][na][1];
                const float a2 = acc[ma][na][2], a3 = acc[ma][na][3];
                if (sec == 0) {
                    unsigned hw, lw;
                    splitpack(a0 * QK_SCALE, a1 * QK_SCALE, hw, lw);
                    g_qhi[(size_t)r0 * KW_D + (within >> 1)] = hw;
                    g_qlo[(size_t)r0 * KW_D + (within >> 1)] = lw;
                    splitpack(a2 * QK_SCALE, a3 * QK_SCALE, hw, lw);
                    g_qhi[(size_t)(r0 + 8) * KW_D + (within >> 1)] = hw;
                    g_qlo[(size_t)(r0 + 8) * KW_D + (within >> 1)] = lw;
                } else if (sec == 1) {
                    const int bh = (r0 >> 11) * HH + h, key = r0 & (SS - 1);
                    const size_t idx = ((size_t)bh * 32 + (hd >> 1)) * SS + key;
                    unsigned hw, lw;
                    splitpack(a0, a1, hw, lw);
                    g_khi[idx] = hw; g_klo[idx] = lw;
                    splitpack(a2, a3, hw, lw);
                    g_khi[idx + 8] = hw; g_klo[idx + 8] = lw;
                } else {
                    const int bh = (r0 >> 11) * HH + h, key = r0 & (SS - 1);
                    const size_t vi = ((size_t)bh * SS + key) * HD + hd;
                    *(float2*)&g_v[vi] = make_float2(a0, a1);
                    *(float2*)&g_v[vi + 8 * HD] = make_float2(a2, a3);
                }
            }
        }
    }
}

// ---------------------------------------------------------------------------
// Flash attention: Mq=128/CTA, 256 thr. All operands prepacked; staging is
// pure cp.async (double buffered), 1 barrier/iter. P via shuffles (no smem).
// smem words: Qlo[128][36] | {Khi,Klo}[2][32][72] | V[2][64][72]
//   (V buf1 doubles as Qhi staging before the main loop)
// ---------------------------------------------------------------------------
#define QS 36
#define KS 72
#define VS 72
#define OFF_K   (128*QS)                 // 4608
#define KBUFW   (2*32*KS)                // 4608 per buf (hi+lo)
#define OFF_V   (OFF_K + 2*KBUFW)        // 13824
#define ATT_W   (OFF_V + 2*64*VS)        // 23040 words
#define ATT_SMEM (ATT_W * 4)             // 92160 B

__global__ void __launch_bounds__(256, 2)
attn_tc()
{
    extern __shared__ unsigned smu[];
    const unsigned smb = (unsigned)__cvta_generic_to_shared(smu);
    unsigned* Qlo = smu;

    const int t = threadIdx.x, lane = t & 31, warp = t >> 5;
    const int g = lane >> 2, tg = lane & 3;
    const int bh = blockIdx.y, qb = blockIdx.x;
    const int b = bh / HH, h = bh - b * HH;
    const int tok0 = b * SS + qb * 128;

    // staging roles
    const int qrow = t >> 1, qhalf = t & 1;        // Q: 128 rows x 2 halves
    const int kdw = t >> 4, kc = (t & 15) * 4;     // K: dw rows x 16 chunks
    const int vr = t >> 2, vq = (t & 3) * 16;      // V: 64 rows x 4 qtrs

    auto issue_kv = [&](int jb, int buf) {
        const unsigned kb = smb + (OFF_K + buf * KBUFW) * 4;
        const size_t ksrc = ((size_t)bh * 32) * SS + jb * 64;
        cp16(kb + (kdw * KS + kc) * 4,            g_khi + ksrc + (size_t)kdw * SS + kc);
        cp16(kb + ((kdw + 16) * KS + kc) * 4,     g_khi + ksrc + (size_t)(kdw + 16) * SS + kc);
        cp16(kb + (32 * KS + kdw * KS + kc) * 4,  g_klo + ksrc + (size_t)kdw * SS + kc);
        cp16(kb + (32 * KS + (kdw + 16) * KS + kc) * 4,
             g_klo + ksrc + (size_t)(kdw + 16) * SS + kc);
        const unsigned vb = smb + (OFF_V + buf * 64 * VS) * 4;
        const float* vsrc = g_v + ((size_t)bh * SS + jb * 64 + vr) * HD + vq;
        #pragma unroll
        for (int i = 0; i < 4; i++)
            cp16(vb + (vr * VS + vq + i * 4) * 4, vsrc + i * 4);
    };

    // ---- prologue: Q (hi into V-buf1 region, lo into Qlo) + K0/V0 ----
    {
        const size_t qsrc = (size_t)(tok0 + qrow) * KW_D + h * 32 + qhalf * 16;
        const unsigned qhi_dst = smb + (OFF_V + 64 * VS) * 4;   // V buf1 region
        #pragma unroll
        for (int i = 0; i < 4; i++) {
            cp16(qhi_dst + (qrow * QS + qhalf * 16 + i * 4) * 4, g_qhi + qsrc + i * 4);
            cp16(smb + (qrow * QS + qhalf * 16 + i * 4) * 4,     g_qlo + qsrc + i * 4);
        }
        issue_kv(0, 0);
        cp_commit();
    }
    asm volatile("cp.async.wait_group 0;");
    __syncthreads();

    unsigned qh[4][4];
    {
        const unsigned* Qhi = smu + OFF_V + 64 * VS;
        #pragma unroll
        for (int c = 0; c < 4; c++) {
            const int base = (warp * 16 + g) * QS + 8 * c + tg;
            qh[c][0] = Qhi[base];      qh[c][1] = Qhi[base + 8 * QS];
            qh[c][2] = Qhi[base + 4];  qh[c][3] = Qhi[base + 8 * QS + 4];
        }
    }
    __syncthreads();   // protect V buf1 region before jb=1 issue

    float mrow[2] = {-1e30f, -1e30f}, lrow[2] = {0.f, 0.f};
    float oacc[8][4];
    #pragma unroll
    for (int i = 0; i < 8; i++)
        #pragma unroll
        for (int j = 0; j < 4; j++) oacc[i][j] = 0.f;

    const int src1 = (lane & 28) | (tg >> 1);
    const int src2 = src1 + 2;
    const bool odd = tg & 1;

    const int NT = SS / 64;
    for (int jb = 0; jb < NT; jb++) {
        if (jb > 0) {
            asm volatile("cp.async.wait_group 0;");
            __syncthreads();
        }
        if (jb + 1 < NT) {
            issue_kv(jb + 1, (jb + 1) & 1);
            cp_commit();
        }

        const int buf = jb & 1;
        const unsigned* Khi = smu + OFF_K + buf * KBUFW;
        const unsigned* Klo = Khi + 32 * KS;
        const unsigned* Vs  = smu + OFF_V + buf * 64 * VS;

        // ---- S = Q K^T (bf16 3-term) ----
        float sacc[8][4];
        #pragma unroll
        for (int i = 0; i < 8; i++)
            #pragma unroll
            for (int j = 0; j < 4; j++) sacc[i][j] = 0.f;

        #pragma unroll
        for (int c = 0; c < 4; c++) {
            unsigned ql[4];
            const int qb2 = (warp * 16 + g) * QS + 8 * c + tg;
            ql[0] = Qlo[qb2];      ql[1] = Qlo[qb2 + 8 * QS];
            ql[2] = Qlo[qb2 + 4];  ql[3] = Qlo[qb2 + 8 * QS + 4];
            #pragma unroll
            for (int na = 0; na < 8; na++) {
                const int kc2 = na * 8 + g;
                const unsigned bh0 = Khi[(8 * c + tg)     * KS + kc2];
                const unsigned bh1 = Khi[(8 * c + tg + 4) * KS + kc2];
                const unsigned bl0 = Klo[(8 * c + tg)     * KS + kc2];
                const unsigned bl1 = Klo[(8 * c + tg + 4) * KS + kc2];
                mmabf(sacc[na], qh[c], bh0, bh1);
                mmabf(sacc[na], qh[c], bl0, bl1);
                mmabf(sacc[na], ql,    bh0, bh1);
            }
        }

        // ---- online softmax ----
        #pragma unroll
        for (int hf = 0; hf < 2; hf++) {
            float rmax = -1e30f;
            #pragma unroll
            for (int na = 0; na < 8; na++)
                rmax = fmaxf(rmax, fmaxf(sacc[na][2*hf], sacc[na][2*hf+1]));
            rmax = fmaxf(rmax, __shfl_xor_sync(0xffffffffu, rmax, 1));
            rmax = fmaxf(rmax, __shfl_xor_sync(0xffffffffu, rmax, 2));
            const float mn = fmaxf(mrow[hf], rmax);
            const float corr = __expf(mrow[hf] - mn);
            mrow[hf] = mn;
            float rs = 0.f;
            #pragma unroll
            for (int na = 0; na < 8; na++) {
                const float e0 = __expf(sacc[na][2*hf]   - mn);
                const float e1 = __expf(sacc[na][2*hf+1] - mn);
                sacc[na][2*hf] = e0; sacc[na][2*hf+1] = e1;
                rs += e0 + e1;
            }
            rs += __shfl_xor_sync(0xffffffffu, rs, 1);
            rs += __shfl_xor_sync(0xffffffffu, rs, 2);
            lrow[hf] = lrow[hf] * corr + rs;
            #pragma unroll
            for (int na = 0; na < 8; na++) {
                oacc[na][2*hf]   *= corr;
                oacc[na][2*hf+1] *= corr;
            }
        }

        // ---- O += P @ V : P tf32 A-frags via shuffles ----
        #pragma unroll
        for (int s = 0; s < 8; s++) {
            const float e0 = __shfl_sync(0xffffffffu, sacc[s][0], src1);
            const float e1 = __shfl_sync(0xffffffffu, sacc[s][1], src1);
            const float e2 = __shfl_sync(0xffffffffu, sacc[s][2], src1);
            const float e3 = __shfl_sync(0xffffffffu, sacc[s][3], src1);
            const float f0 = __shfl_sync(0xffffffffu, sacc[s][0], src2);
            const float f1 = __shfl_sync(0xffffffffu, sacc[s][1], src2);
            const float f2 = __shfl_sync(0xffffffffu, sacc[s][2], src2);
            const float f3 = __shfl_sync(0xffffffffu, sacc[s][3], src2);
            unsigned ap[4];
            ap[0] = f2tf(odd ? e1 : e0);
            ap[1] = f2tf(odd ? e3 : e2);
            ap[2] = f2tf(odd ? f1 : f0);
            ap[3] = f2tf(odd ? f3 : f2);
            #pragma unroll
            for (int na = 0; na < 8; na++) {
                const unsigned v0 = Vs[(s * 8 + tg)     * VS + na * 8 + g];
                const unsigned v1 = Vs[(s * 8 + tg + 4) * VS + na * 8 + g];
                mma8(oacc[na], ap, v0, v1);
            }
        }
    }

    // ---- epilogue: write ctx split, GEMM-A layout ----
    const float inv0 = 1.0f / lrow[0], inv1 = 1.0f / lrow[1];
    const int tok = tok0 + warp * 16 + g;
    #pragma unroll
    for (int na = 0; na < 8; na++) {
        const int w = h * 32 + na * 4 + tg;
        unsigned hw, lw;
        splitpack(oacc[na][0] * inv0, oacc[na][1] * inv0, hw, lw);
        g_chi[(size_t)tok * KW_D + w] = hw;
        g_clo[(size_t)tok * KW_D + w] = lw;
        splitpack(oacc[na][2] * inv1, oacc[na][3] * inv1, hw, lw);
        g_chi[(size_t)(tok + 8) * KW_D + w] = hw;
        g_clo[(size_t)(tok + 8) * KW_D + w] = lw;
    }
}

// ---------------------------------------------------------------------------
extern "C" void kernel_launch(void* const* d_in, const int* in_sizes, int n_in,
                              void* d_out, int out_size)
{
    const float* x     = (const float*)d_in[0];
    const float* w_qkv = (const float*)d_in[1];
    const float* w_out = (const float*)d_in[2];
    const float* b_out = (const float*)d_in[3];
    float* out = (float*)d_out;

    unsigned *xhi, *xlo, *wqhi, *wqlo, *wohi, *wolo, *chi, *clo;
    cudaGetSymbolAddress((void**)&xhi,  g_xhi);
    cudaGetSymbolAddress((void**)&xlo,  g_xlo);
    cudaGetSymbolAddress((void**)&wqhi, g_wqhi);
    cudaGetSymbolAddress((void**)&wqlo, g_wqlo);
    cudaGetSymbolAddress((void**)&wohi, g_wohi);
    cudaGetSymbolAddress((void**)&wolo, g_wolo);
    cudaGetSymbolAddress((void**)&chi,  g_chi);
    cudaGetSymbolAddress((void**)&clo,  g_clo);

    cudaFuncSetAttribute(gemm_pk<0>, cudaFuncAttributeMaxDynamicSharedMemorySize, GEMM_SMEM);
    cudaFuncSetAttribute(gemm_pk<1>, cudaFuncAttributeMaxDynamicSharedMemorySize, GEMM_SMEM);
    cudaFuncSetAttribute(attn_tc,    cudaFuncAttributeMaxDynamicSharedMemorySize, ATT_SMEM);

    // 0) pre-split inputs
    const int nwx = M_TOK * KW_D;
    conv_A<<<(nwx + 255) / 256, 256>>>(x, xhi, xlo, nwx);
    const int nwq = KW_D * N_QKV;
    conv_B<<<(nwq + 255) / 256, 256>>>(w_qkv, wqhi, wqlo, KW_D, N_QKV);
    const int nwo = KW_D * DD;
    conv_B<<<(nwo + 255) / 256, 256>>>(w_out, wohi, wolo, KW_D, DD);

    // 1) QKV projection (epilogue routes split Q/K + dense V)
    gemm_pk<1><<<dim3(N_QKV / 128, M_TOK / 128), 256, GEMM_SMEM>>>(
        xhi, xlo, wqhi, wqlo, nullptr, nullptr, KW_D, N_QKV);

    // 2) attention
    attn_tc<<<dim3(SS / 128, BB * HH), 256, ATT_SMEM>>>();

    // 3) output projection + bias
    gemm_pk<0><<<dim3(DD / 128, M_TOK / 128), 256, GEMM_SMEM>>>(
        chi, clo, wohi, wolo, b_out, out, KW_D, DD);
}